// round 3
// baseline (speedup 1.0000x reference)
#include <cuda_runtime.h>
#include <cstdint>

// Problem constants (fixed by the dataset)
#define T_ 8
#define E_ 8388608
#define N_ 262144
#define F_ 64

// 8 MB scratch for segment sums, layout agg[n][t] row-major (32B per node).
__device__ float g_agg[(size_t)N_ * T_];

// ---------------------------------------------------------------------------
// Kernel 1: zero the aggregation buffer (every replay — graph-captured)
// ---------------------------------------------------------------------------
__global__ void zero_agg_kernel() {
    int i = blockIdx.x * blockDim.x + threadIdx.x;   // N_*T_/4 = 524288 float4s
    reinterpret_cast<float4*>(g_agg)[i] = make_float4(0.f, 0.f, 0.f, 0.f);
}

// ---------------------------------------------------------------------------
// Kernel 2: scatter-add. One thread per edge. 8 coalesced feature loads,
// one 8B index load (int32 pair!), two vector REDs into L2-resident agg.
// ---------------------------------------------------------------------------
__global__ void scatter_kernel(const float* __restrict__ feat,
                               const int2* __restrict__ idx) {
    int e = blockIdx.x * blockDim.x + threadIdx.x;
    if (e >= E_) return;

    // (row, col) pair: JAX x64-disabled => int32 indices
    int2 rc = __ldcs(&idx[e]);
    int row = rc.x & (N_ - 1);   // N_ is pow2; no-op for valid rows, crash-proof otherwise

    // 8 strided-but-coalesced streaming loads, MLP=8
    float f0 = __ldcs(feat + 0 * (size_t)E_ + e);
    float f1 = __ldcs(feat + 1 * (size_t)E_ + e);
    float f2 = __ldcs(feat + 2 * (size_t)E_ + e);
    float f3 = __ldcs(feat + 3 * (size_t)E_ + e);
    float f4 = __ldcs(feat + 4 * (size_t)E_ + e);
    float f5 = __ldcs(feat + 5 * (size_t)E_ + e);
    float f6 = __ldcs(feat + 6 * (size_t)E_ + e);
    float f7 = __ldcs(feat + 7 * (size_t)E_ + e);

    float* dst = g_agg + (size_t)row * T_;   // 32B aligned
    asm volatile("red.global.add.v4.f32 [%0], {%1,%2,%3,%4};"
                 :: "l"(dst),     "f"(f0), "f"(f1), "f"(f2), "f"(f3) : "memory");
    asm volatile("red.global.add.v4.f32 [%0], {%1,%2,%3,%4};"
                 :: "l"(dst + 4), "f"(f4), "f"(f5), "f"(f6), "f"(f7) : "memory");
}

// ---------------------------------------------------------------------------
// Kernel 3: out[n,f] = sum_t agg[n,t] * kernel[t,f] + bias[f]
// Block = 256 threads, handles 32 nodes x 64 features.
// ---------------------------------------------------------------------------
__global__ void gemm_kernel(const float* __restrict__ kern,
                            const float* __restrict__ bias,
                            float* __restrict__ out) {
    __shared__ float sK[T_ * F_];   // 512 floats
    __shared__ float sA[32 * T_];   // 256 floats

    int tid = threadIdx.x;
    int nbase = blockIdx.x * 32;

    sK[tid]       = kern[tid];
    sK[tid + 256] = kern[tid + 256];
    sA[tid]       = g_agg[(size_t)nbase * T_ + tid];
    __syncthreads();

    int f   = tid & 63;    // 0..63
    int nl0 = tid >> 6;    // 0..3
    float b = bias[f];

    #pragma unroll
    for (int i = 0; i < 8; ++i) {
        int nl = nl0 + (i << 2);         // 0..31
        float acc = b;
        #pragma unroll
        for (int t = 0; t < T_; ++t)
            acc = fmaf(sA[nl * T_ + t], sK[t * F_ + f], acc);
        out[((size_t)(nbase + nl)) * F_ + f] = acc;
    }
}

// ---------------------------------------------------------------------------
// Launch contract — inputs resolved BY ELEMENT COUNT (robust to whether the
// scalar `out_size` occupies an input slot):
//   edge_features:  T*E = 67108864 f32
//   sparse_indices: E*2 = 16777216 i32
//   kernel:         T*F = 512 f32
//   bias:           F   = 64 f32
// Output: N*F f32.
// ---------------------------------------------------------------------------
extern "C" void kernel_launch(void* const* d_in, const int* in_sizes, int n_in,
                              void* d_out, int out_size) {
    const float* feat = nullptr;
    const int2*  idx  = nullptr;
    const float* kern = nullptr;
    const float* bias = nullptr;

    for (int i = 0; i < n_in; ++i) {
        long long s = in_sizes[i];
        if      (s == (long long)T_ * E_) feat = (const float*)d_in[i];
        else if (s == (long long)2 * E_)  idx  = (const int2*)d_in[i];
        else if (s == T_ * F_)            kern = (const float*)d_in[i];
        else if (s == F_)                 bias = (const float*)d_in[i];
    }
    if (!feat) feat = (const float*)d_in[0];
    if (!idx)  idx  = (const int2*)d_in[1];
    if (!kern) kern = (const float*)d_in[n_in >= 5 ? 3 : 2];
    if (!bias) bias = (const float*)d_in[n_in >= 5 ? 4 : 3];

    float* out = (float*)d_out;
    (void)out_size;

    zero_agg_kernel<<<(N_ * T_ / 4) / 256, 256>>>();
    scatter_kernel<<<E_ / 256, 256>>>(feat, idx);
    gemm_kernel<<<N_ / 32, 256>>>(kern, bias, out);
}